// round 7
// baseline (speedup 1.0000x reference)
#include <cuda_runtime.h>
#include <cuda_fp16.h>
#include <stdint.h>
#include <math.h>

#define B_ 64
#define N_ 4096
#define V_ 21
#define S_ 50
#define E_ 64
#define H_ 128
#define THREADS 512
#define NCTAS 148
#define PADH 136      // halves per padded smem row (272B)

// smem layout (bytes)
#define SMU_BYTES (512*PADH*2)          // 139264: U-concat
#define HTILE_BYTES (64*PADH*2)         // 17408
#define BUF_BYTES (2*HTILE_BYTES)       // 34816 (HT+HR)
#define SM_TOTAL (SMU_BYTES + 2*BUF_BYTES)   // 208896

// deep-phase layout inside the buffer region (offsets from SMU_BYTES)
#define DP_H    0        // 64 rows x 256B fp16
#define DP_C    16384    // 64 rows x 512B fp32
#define DP_A    49152    // HT 32x272 = 8704, HR 8704
#define DP_ROOT 66560    // 128 floats

#define TOTROWS 258048   // sum of level-output rows: 64*(2048+1024+512+256+128+64)
#define NFLAGS  4032

// ---------------- static device scratch ----------------
__device__ float  g_tai[S_*H_], g_tao[S_*H_], g_tau[S_*H_], g_taf[S_*H_];
__device__ __half g_h016[V_*H_];
__device__ float  g_c0[V_*H_];
__device__ __half g_H[TOTROWS*H_];      // per-level disjoint output regions
__device__ float  g_C[TOTROWS*H_];
__device__ unsigned g_flags[NFLAGS];    // per-tile completion flags (zero-init, reset each launch)
__device__ unsigned g_bar;
__device__ unsigned g_done;

__device__ __forceinline__ float tha(float x){
  float y; asm("tanh.approx.f32 %0, %1;" : "=f"(y) : "f"(x)); return y;
}
__device__ __forceinline__ float sga(float x){ return 0.5f*tha(0.5f*x) + 0.5f; }

__device__ __forceinline__ unsigned saddr(const void* p){
  return (unsigned)__cvta_generic_to_shared(p);
}
__device__ __forceinline__ void ldsm4(unsigned addr, unsigned &r0, unsigned &r1, unsigned &r2, unsigned &r3){
  asm volatile("ldmatrix.sync.aligned.m8n8.x4.shared.b16 {%0,%1,%2,%3}, [%4];"
    : "=r"(r0),"=r"(r1),"=r"(r2),"=r"(r3) : "r"(addr));
}
__device__ __forceinline__ void mma16816(float d[4], const unsigned a[4], unsigned b0, unsigned b1){
  asm volatile("mma.sync.aligned.m16n8k16.row.col.f32.f16.f16.f32 "
    "{%0,%1,%2,%3}, {%4,%5,%6,%7}, {%8,%9}, {%0,%1,%2,%3};"
    : "+f"(d[0]),"+f"(d[1]),"+f"(d[2]),"+f"(d[3])
    : "r"(a[0]),"r"(a[1]),"r"(a[2]),"r"(a[3]), "r"(b0),"r"(b1));
}
__device__ __forceinline__ uint32_t hadd2u(uint32_t a, uint32_t b){
  __half2 r = __hadd2(*reinterpret_cast<__half2*>(&a), *reinterpret_cast<__half2*>(&b));
  return *reinterpret_cast<uint32_t*>(&r);
}
__device__ __forceinline__ uint32_t hsub2u(uint32_t a, uint32_t b){
  __half2 r = __hsub2(*reinterpret_cast<__half2*>(&a), *reinterpret_cast<__half2*>(&b));
  return *reinterpret_cast<uint32_t*>(&r);
}
__device__ __forceinline__ uint4 ldcg4(const uint4* p){
  uint4 v;
  asm volatile("ld.global.cg.v4.u32 {%0,%1,%2,%3}, [%4];"
    : "=r"(v.x),"=r"(v.y),"=r"(v.z),"=r"(v.w) : "l"(p));
  return v;
}
__device__ __forceinline__ float2 ldcg2f(const float2* p){
  float2 v;
  asm volatile("ld.global.cg.v2.f32 {%0,%1}, [%2];" : "=f"(v.x),"=f"(v.y) : "l"(p));
  return v;
}
__device__ __forceinline__ void stcg2f(float2* p, float2 v){
  asm volatile("st.global.cg.v2.f32 [%0], {%1,%2};" :: "l"(p), "f"(v.x), "f"(v.y) : "memory");
}
__device__ __forceinline__ void stcgu(uint32_t* p, uint32_t v){
  asm volatile("st.global.cg.u32 [%0], %1;" :: "l"(p), "r"(v) : "memory");
}
__device__ __forceinline__ void waitflag(unsigned idx){
  volatile unsigned* f = &g_flags[idx];
  if (*f) return;
  while (*f == 0u) __nanosleep(128);
}

// ---------------- shared GEMM tile ----------------
__device__ __forceinline__ void gemm_tile(const __half* sU, const __half* sHT, const __half* sHR,
                                          int lane, int wm, int wn,
                                          float acc1[12][4], float acc2[8][4]){
  #pragma unroll
  for (int i = 0; i < 12; i++){ acc1[i][0]=0.f; acc1[i][1]=0.f; acc1[i][2]=0.f; acc1[i][3]=0.f; }
  #pragma unroll
  for (int i = 0; i < 8; i++){ acc2[i][0]=0.f; acc2[i][1]=0.f; acc2[i][2]=0.f; acc2[i][3]=0.f; }
  #pragma unroll
  for (int k16 = 0; k16 < 8; k16++){
    const int kh = k16*16;
    const int arow = 16*wm + (lane & 15);
    const int acol = kh + (lane >> 4)*8;
    unsigned aT[4], aR[4], aL[4];
    ldsm4(saddr(&sHT[arow*PADH + acol]), aT[0],aT[1],aT[2],aT[3]);
    ldsm4(saddr(&sHR[arow*PADH + acol]), aR[0],aR[1],aR[2],aR[3]);
    #pragma unroll
    for (int i = 0; i < 4; i++) aL[i] = hsub2u(aT[i], aR[i]);   // hl = ht - hr

    const int brow_in = ((lane>>4)&1)*8 + (lane&7);
    const int bcol    = kh + ((lane>>3)&1)*8;
    #pragma unroll
    for (int g = 0; g < 3; g++){
      #pragma unroll
      for (int sp = 0; sp < 2; sp++){
        int R0 = 128*g + 32*wn + 16*sp;
        unsigned r0,r1,r2,r3;
        ldsm4(saddr(&sU[(R0 + brow_in)*PADH + bcol]), r0,r1,r2,r3);
        mma16816(acc1[g*4 + 2*sp + 0], aT, r0, r1);
        mma16816(acc1[g*4 + 2*sp + 1], aT, r2, r3);
      }
    }
    #pragma unroll
    for (int sp = 0; sp < 2; sp++){
      int R0 = 384 + 32*wn + 16*sp;
      unsigned r0,r1,r2,r3;
      ldsm4(saddr(&sU[(R0 + brow_in)*PADH + bcol]), r0,r1,r2,r3);
      mma16816(acc2[2*sp + 0], aL, r0, r1);
      mma16816(acc2[2*sp + 1], aL, r2, r3);
      mma16816(acc2[4 + 2*sp + 0], aR, r0, r1);
      mma16816(acc2[4 + 2*sp + 1], aR, r2, r3);
    }
  }
}

// stage 64-node tile from gmem
__device__ __forceinline__ void stage_tile(char* bufbase, const __half* Hsrc,
    const int* tokens, int lvl, int node0, int logm, int m, int tid){
  const uint4* H4 = (const uint4*)Hsrc;
  char* sHT = bufbase;
  char* sHR = bufbase + HTILE_BYTES;
  #pragma unroll 2
  for (int idx = tid; idx < 64*16; idx += THREADS){
    int r = idx >> 4, q = idx & 15;
    int n_g = node0 + r;
    int i0, i1;
    if (lvl == 0){
      int b = n_g >> logm, j = n_g & (m-1);
      i0 = __ldg(&tokens[b*N_ + 2*j]);
      i1 = __ldg(&tokens[b*N_ + 2*j + 1]);
    } else { i0 = 2*n_g; i1 = 2*n_g + 1; }
    uint4 a  = ldcg4(&H4[i0*16 + q]);
    uint4 b4 = ldcg4(&H4[i1*16 + q]);
    uint4 s;
    s.x = hadd2u(a.x, b4.x); s.y = hadd2u(a.y, b4.y);
    s.z = hadd2u(a.z, b4.z); s.w = hadd2u(a.w, b4.w);
    int boff = r*(PADH*2) + q*16;
    *(uint4*)(sHT + boff) = s;
    *(uint4*)(sHR + boff) = b4;
  }
}

// ---------------- fused persistent kernel ----------------
extern __shared__ char smx[];
__global__ __launch_bounds__(THREADS, 1) void fused_kernel(
  const int* __restrict__ tokens, const int* __restrict__ symbols,
  const float* __restrict__ emb, const float* __restrict__ sym_emb,
  const float* __restrict__ Wp, const float* __restrict__ bp,
  const float* __restrict__ Wi, const float* __restrict__ bi,
  const float* __restrict__ Ui, const float* __restrict__ Wf,
  const float* __restrict__ bf, const float* __restrict__ Uf,
  const float* __restrict__ Wo, const float* __restrict__ bo,
  const float* __restrict__ Uo, const float* __restrict__ Wu,
  const float* __restrict__ bu, const float* __restrict__ Uu,
  const float* __restrict__ Wout, const float* __restrict__ bout,
  float* __restrict__ out)
{
  const int tid = threadIdx.x;
  const int lane = tid & 31, wid = tid >> 5;
  const int wm = wid >> 2, wn = wid & 3;
  __half* sU = (__half*)smx;

  // ---- phase 0: stage fp16 U-concat into smem ----
  for (int idx = tid; idx < 512*32; idx += THREADS){
    int r = idx >> 5, q = idx & 31;
    const float* src = (r < 128) ? Ui + r*H_
                      : (r < 256) ? Uo + (r-128)*H_
                      : (r < 384) ? Uu + (r-256)*H_
                      :             Uf + (r-384)*H_;
    float4 v = __ldg((const float4*)src + q);
    __half2 h0 = __floats2half2_rn(v.x, v.y);
    __half2 h1 = __floats2half2_rn(v.z, v.w);
    uint2 u;
    u.x = *reinterpret_cast<uint32_t*>(&h0);
    u.y = *reinterpret_cast<uint32_t*>(&h1);
    *(uint2*)(smx + (r*PADH + q*4)*2) = u;
  }

  // ---- phase 0b: tables ----
  if (blockIdx.x < V_ + S_){
    float* se = (float*)(smx + SMU_BYTES);
    float* sx = se + E_;
    const int v_or_s = blockIdx.x;
    const int h = tid;
    if (tid < E_)
      se[tid] = (v_or_s < V_) ? emb[v_or_s*E_ + tid] : sym_emb[(v_or_s - V_)*E_ + tid];
    __syncthreads();
    if (tid < H_){
      float x = bp[h];
      #pragma unroll 8
      for (int e = 0; e < E_; e++) x += se[e]*Wp[h*E_ + e];
      sx[h] = x;
    }
    __syncthreads();
    if (tid < H_){
      if (v_or_s < V_){
        float ai_ = bi[h], ao_ = bo[h], au_ = bu[h];
        #pragma unroll 8
        for (int k = 0; k < H_; k++){
          float xv = sx[k];
          ai_ += xv*Wi[h*H_+k]; ao_ += xv*Wo[h*H_+k]; au_ += xv*Wu[h*H_+k];
        }
        float gi = 1.f/(1.f+expf(-ai_)), go = 1.f/(1.f+expf(-ao_)), gu = tanhf(au_);
        float c = gi*gu;
        g_c0[v_or_s*H_+h] = c;
        g_h016[v_or_s*H_+h] = __float2half(go*tanhf(c));
      } else {
        int s = v_or_s - V_;
        float ai_ = bi[h], ao_ = bo[h], au_ = bu[h], af_ = bf[h];
        #pragma unroll 8
        for (int k = 0; k < H_; k++){
          float xv = sx[k];
          ai_ += xv*Wi[h*H_+k]; ao_ += xv*Wo[h*H_+k];
          au_ += xv*Wu[h*H_+k]; af_ += xv*Wf[h*H_+k];
        }
        g_tai[s*H_+h] = ai_; g_tao[s*H_+h] = ao_;
        g_tau[s*H_+h] = au_; g_taf[s*H_+h] = af_;
      }
    }
  }

  // ---- ONE grid barrier: tables + U ready ----
  __syncthreads();
  if (tid == 0){
    __threadfence();
    atomicAdd(&g_bar, 1u);
    while (*(volatile unsigned*)&g_bar < NCTAS) __nanosleep(32);
    __threadfence();
  }
  __syncthreads();

  // ---- big levels 0..5 (m = 2048..64), barrier-free dataflow ----
  int m = 2048, off = 0;
  int srcRows = 0, dstRows = 0;     // disjoint per-level output regions
  int fSrc = 0, fDst = 0;           // flag bases
  for (int lvl = 0; lvl < 6; lvl++){
    const __half* Hsrc = (lvl == 0) ? g_h016 : g_H + (size_t)srcRows*H_;
    const float*  Csrc = (lvl == 0) ? g_c0   : g_C + (size_t)srcRows*H_;
    __half* Hdst = g_H + (size_t)dstRows*H_;
    float*  Cdst = g_C + (size_t)dstRows*H_;

    const int tiles = (B_*m) >> 6;
    const int logm  = 31 - __clz(m);

    int t = blockIdx.x;
    int buf = 0;
    if (t < tiles){
      if (lvl > 0){ waitflag(fSrc + 2*t); waitflag(fSrc + 2*t + 1); }
      stage_tile(smx + SMU_BYTES + buf*BUF_BYTES, Hsrc, tokens, lvl, t << 6, logm, m, tid);
    }
    __syncthreads();

    for (; t < tiles; t += NCTAS){
      const int node0 = t << 6;
      char* bb = smx + SMU_BYTES + buf*BUF_BYTES;

      float acc1[12][4], acc2[8][4];
      gemm_tile(sU, (const __half*)bb, (const __half*)(bb + HTILE_BYTES), lane, wm, wn, acc1, acc2);

      // prefetch next tile (wait its sources first)
      {
        int tn = t + NCTAS;
        if (tn < tiles){
          if (lvl > 0){ waitflag(fSrc + 2*tn); waitflag(fSrc + 2*tn + 1); }
          stage_tile(smx + SMU_BYTES + (buf^1)*BUF_BYTES, Hsrc, tokens, lvl, tn << 6, logm, m, tid);
        }
      }

      if (lvl == 5) __syncthreads();   // lvl5 epilogue writes into the A-buffer region

      // epilogue
      #pragma unroll
      for (int half = 0; half < 2; half++){
        int nl = 16*wm + (lane >> 2) + 8*half;
        int n_g = node0 + nl;
        int b = n_g >> logm, j = n_g & (m-1);
        int sym = __ldg(&symbols[b*(N_-1) + off + j]);
        int i0, i1;
        if (lvl == 0){ i0 = __ldg(&tokens[b*N_ + 2*j]); i1 = __ldg(&tokens[b*N_ + 2*j + 1]); }
        else         { i0 = 2*n_g; i1 = 2*n_g + 1; }
        const float2* cl2p = (const float2*)(Csrc + (size_t)i0*H_);
        const float2* cr2p = (const float2*)(Csrc + (size_t)i1*H_);
        const float2* ai2  = (const float2*)(g_tai + sym*H_);
        const float2* ao2  = (const float2*)(g_tao + sym*H_);
        const float2* au2  = (const float2*)(g_tau + sym*H_);
        const float2* af2  = (const float2*)(g_taf + sym*H_);
        const int e = 2*half;
        // batched child-c / table loads
        float2 cl[4], cr[4], tf[4];
        #pragma unroll
        for (int s = 0; s < 4; s++){
          int c2 = 16*wn + 4*s + (lane & 3);
          cl[s] = ldcg2f(cl2p + c2);
          cr[s] = ldcg2f(cr2p + c2);
          tf[s] = __ldg(af2 + c2);
        }
        if (lvl < 5){
          float2*  co = (float2*)(Cdst + (size_t)n_g*H_);
          uint32_t* ho = (uint32_t*)(Hdst + (size_t)n_g*H_);
          #pragma unroll
          for (int s = 0; s < 4; s++){
            int c2 = 16*wn + 4*s + (lane & 3);
            float2 ta = __ldg(ai2 + c2), tu = __ldg(au2 + c2), to = __ldg(ao2 + c2);
            float pi0 = acc1[0*4+s][e]   + ta.x, pi1 = acc1[0*4+s][e+1] + ta.y;
            float pu0 = acc1[2*4+s][e]   + tu.x, pu1 = acc1[2*4+s][e+1] + tu.y;
            float fl0 = acc2[s][e]       + tf[s].x, fl1 = acc2[s][e+1]   + tf[s].y;
            float fr0 = acc2[4+s][e]     + tf[s].x, fr1 = acc2[4+s][e+1] + tf[s].y;
            float cn0 = sga(pi0)*tha(pu0) + sga(fl0)*cl[s].x + sga(fr0)*cr[s].x;
            float cn1 = sga(pi1)*tha(pu1) + sga(fl1)*cl[s].y + sga(fr1)*cr[s].y;
            float po0 = acc1[1*4+s][e]   + to.x, po1 = acc1[1*4+s][e+1] + to.y;
            float h0 = sga(po0)*tha(cn0);
            float h1 = sga(po1)*tha(cn1);
            stcg2f(co + c2, make_float2(cn0, cn1));
            __half2 hh = __floats2half2_rn(h0, h1);
            stcgu(ho + c2, *reinterpret_cast<uint32_t*>(&hh));
          }
        } else {
          // lvl5: write straight into the deep-phase smem region (sole consumer = this CTA)
          char* dpH = smx + SMU_BYTES + DP_H;
          char* dpC = smx + SMU_BYTES + DP_C;
          float2*  co = (float2*)(dpC + nl*512);
          uint32_t* ho = (uint32_t*)(dpH + nl*256);
          #pragma unroll
          for (int s = 0; s < 4; s++){
            int c2 = 16*wn + 4*s + (lane & 3);
            float2 ta = __ldg(ai2 + c2), tu = __ldg(au2 + c2), to = __ldg(ao2 + c2);
            float pi0 = acc1[0*4+s][e]   + ta.x, pi1 = acc1[0*4+s][e+1] + ta.y;
            float pu0 = acc1[2*4+s][e]   + tu.x, pu1 = acc1[2*4+s][e+1] + tu.y;
            float fl0 = acc2[s][e]       + tf[s].x, fl1 = acc2[s][e+1]   + tf[s].y;
            float fr0 = acc2[4+s][e]     + tf[s].x, fr1 = acc2[4+s][e+1] + tf[s].y;
            float cn0 = sga(pi0)*tha(pu0) + sga(fl0)*cl[s].x + sga(fr0)*cr[s].x;
            float cn1 = sga(pi1)*tha(pu1) + sga(fl1)*cl[s].y + sga(fr1)*cr[s].y;
            float po0 = acc1[1*4+s][e]   + to.x, po1 = acc1[1*4+s][e+1] + to.y;
            float h0 = sga(po0)*tha(cn0);
            float h1 = sga(po1)*tha(cn1);
            co[c2] = make_float2(cn0, cn1);
            __half2 hh = __floats2half2_rn(h0, h1);
            ho[c2] = *reinterpret_cast<uint32_t*>(&hh);
          }
        }
      }
      __threadfence();
      __syncthreads();
      if (lvl < 5 && tid == 0)
        *(volatile unsigned*)&g_flags[fDst + t] = 1u;
      buf ^= 1;
    }

    off += m;
    srcRows = dstRows; dstRows += B_*m;
    fSrc = fDst; fDst += tiles;
    m >>= 1;
  }

  // ---- deep phase: per-batch CTA, m = 32..1, all in smem (lvl5 data already here) ----
  if (blockIdx.x < B_){
    const int b = blockIdx.x;
    char* dpH = smx + SMU_BYTES + DP_H;
    char* dpC = smx + SMU_BYTES + DP_C;
    char* dpHT = smx + SMU_BYTES + DP_A;
    char* dpHR = dpHT + 8704;
    float* sRoot = (float*)(smx + SMU_BYTES + DP_ROOT);

    int offd = 4032;
    for (int dm = 32; dm >= 1; dm >>= 1){
      for (int idx = tid; idx < dm*16; idx += THREADS){
        int r = idx >> 4, q = idx & 15;
        uint4 a  = *(const uint4*)(dpH + (2*r)*256 + q*16);
        uint4 b4 = *(const uint4*)(dpH + (2*r+1)*256 + q*16);
        uint4 s;
        s.x = hadd2u(a.x, b4.x); s.y = hadd2u(a.y, b4.y);
        s.z = hadd2u(a.z, b4.z); s.w = hadd2u(a.w, b4.w);
        int boff = r*(PADH*2) + q*16;
        *(uint4*)(dpHT + boff) = s;
        *(uint4*)(dpHR + boff) = b4;
      }
      __syncthreads();

      const int nrb = (dm + 15) >> 4;
      const bool part = (wm < nrb);
      float acc1[12][4], acc2[8][4];
      if (part)
        gemm_tile(sU, (const __half*)dpHT, (const __half*)dpHR, lane, wm, wn, acc1, acc2);

      float2 cpl[2][4], cpr[2][4];
      if (part){
        #pragma unroll
        for (int half = 0; half < 2; half++){
          int nl = 16*wm + (lane >> 2) + 8*half;
          if (nl < dm){
            #pragma unroll
            for (int s = 0; s < 4; s++){
              int c2 = 16*wn + 4*s + (lane & 3);
              cpl[half][s] = ((const float2*)(dpC + (2*nl)*512))[c2];
              cpr[half][s] = ((const float2*)(dpC + (2*nl+1)*512))[c2];
            }
          }
        }
      }
      __syncthreads();

      if (part){
        #pragma unroll
        for (int half = 0; half < 2; half++){
          int nl = 16*wm + (lane >> 2) + 8*half;
          if (nl >= dm) continue;
          int sym = __ldg(&symbols[b*(N_-1) + offd + nl]);
          const float2* ai2 = (const float2*)(g_tai + sym*H_);
          const float2* ao2 = (const float2*)(g_tao + sym*H_);
          const float2* au2 = (const float2*)(g_tau + sym*H_);
          const float2* af2 = (const float2*)(g_taf + sym*H_);
          float2* co = (float2*)(dpC + nl*512);
          uint32_t* ho = (uint32_t*)(dpH + nl*256);
          const int e = 2*half;
          #pragma unroll
          for (int s = 0; s < 4; s++){
            int c2 = 16*wn + 4*s + (lane & 3);
            float2 ta = __ldg(ai2 + c2), tu = __ldg(au2 + c2);
            float2 tf = __ldg(af2 + c2), to = __ldg(ao2 + c2);
            float pi0 = acc1[0*4+s][e]   + ta.x, pi1 = acc1[0*4+s][e+1] + ta.y;
            float pu0 = acc1[2*4+s][e]   + tu.x, pu1 = acc1[2*4+s][e+1] + tu.y;
            float fl0 = acc2[s][e]       + tf.x, fl1 = acc2[s][e+1]     + tf.y;
            float fr0 = acc2[4+s][e]     + tf.x, fr1 = acc2[4+s][e+1]   + tf.y;
            float cn0 = sga(pi0)*tha(pu0) + sga(fl0)*cpl[half][s].x + sga(fr0)*cpr[half][s].x;
            float cn1 = sga(pi1)*tha(pu1) + sga(fl1)*cpl[half][s].y + sga(fr1)*cpr[half][s].y;
            float po0 = acc1[1*4+s][e]   + to.x, po1 = acc1[1*4+s][e+1] + to.y;
            float h0 = sga(po0)*tha(cn0);
            float h1 = sga(po1)*tha(cn1);
            co[c2] = make_float2(cn0, cn1);
            __half2 hh = __floats2half2_rn(h0, h1);
            ho[c2] = *reinterpret_cast<uint32_t*>(&hh);
            if (dm == 1)
              ((float2*)sRoot)[c2] = make_float2(h0, h1);
          }
        }
      }
      __syncthreads();
      offd += dm;
    }

    // projection for this batch
    if (tid < H_){
      const int o = tid;
      float acc = bout[o];
      const float* w = Wout + o*H_;
      #pragma unroll 8
      for (int k = 0; k < H_; k++) acc += sRoot[k]*w[k];
      out[b*H_ + o] = acc;
    }
  }

  // ---- reset flags/counters for next graph replay (last CTA only; all work done) ----
  __syncthreads();
  __shared__ unsigned s_last;
  if (tid == 0)
    s_last = (atomicAdd(&g_done, 1u) + 1u == NCTAS) ? 1u : 0u;
  __syncthreads();
  if (s_last){
    for (int i = tid; i < NFLAGS; i += THREADS) g_flags[i] = 0u;
    if (tid == 0){
      atomicExch(&g_bar, 0u);
      atomicExch(&g_done, 0u);
    }
  }
}

// ---------------- host orchestration ----------------
extern "C" void kernel_launch(void* const* d_in, const int* in_sizes, int n_in,
                              void* d_out, int out_size) {
  const int*   tokens  = (const int*)  d_in[0];
  const int*   symbols = (const int*)  d_in[1];
  const float* emb     = (const float*)d_in[2];
  const float* sym_emb = (const float*)d_in[3];
  const float* Wp   = (const float*)d_in[4];
  const float* bp   = (const float*)d_in[5];
  const float* Wi   = (const float*)d_in[6];
  const float* bi   = (const float*)d_in[7];
  const float* Ui   = (const float*)d_in[8];
  const float* Wf   = (const float*)d_in[9];
  const float* bf   = (const float*)d_in[10];
  const float* Uf   = (const float*)d_in[11];
  const float* Wo   = (const float*)d_in[12];
  const float* bo   = (const float*)d_in[13];
  const float* Uo   = (const float*)d_in[14];
  const float* Wu   = (const float*)d_in[15];
  const float* bu   = (const float*)d_in[16];
  const float* Uu   = (const float*)d_in[17];
  const float* Wout = (const float*)d_in[18];
  const float* bout = (const float*)d_in[19];

  cudaFuncSetAttribute(fused_kernel, cudaFuncAttributeMaxDynamicSharedMemorySize, SM_TOTAL);
  fused_kernel<<<NCTAS, THREADS, SM_TOTAL>>>(
      tokens, symbols, emb, sym_emb, Wp, bp, Wi, bi, Ui, Wf, bf, Uf,
      Wo, bo, Uo, Wu, bu, Uu, Wout, bout, (float*)d_out);
}

// round 8
// speedup vs baseline: 1.5045x; 1.5045x over previous
#include <cuda_runtime.h>
#include <cuda_fp16.h>
#include <stdint.h>
#include <math.h>

#define B_ 64
#define N_ 4096
#define V_ 21
#define S_ 50
#define E_ 64
#define H_ 128
#define THREADS 512
#define NCTAS 148
#define PADH 136      // halves per padded smem row (272B)

#define NT0 22050     // 21*21*50 unique (tokL, tokR, symbol) leaf-pair triples
#define T0TILES 345   // ceil(22050/64)

// smem layout (bytes)
#define SMU_BYTES (512*PADH*2)          // 139264: U-concat
#define HTILE_BYTES (64*PADH*2)         // 17408
#define BUF_BYTES (2*HTILE_BYTES)       // 34816 (HT+HR)
#define SM_TOTAL (SMU_BYTES + 2*BUF_BYTES)   // 208896

// deep-phase layout inside the buffer region (offsets from SMU_BYTES)
#define DP_H    0        // 64 rows x 256B fp16
#define DP_C    16384    // 64 rows x 512B fp32
#define DP_A    49152    // HT 32x272 = 8704, HR 8704
#define DP_ROOT 66560    // 128 floats

// ---------------- static device scratch ----------------
__device__ float  g_tai[S_*H_], g_tao[S_*H_], g_tau[S_*H_], g_taf[S_*H_];
__device__ __half g_h016[V_*H_];
__device__ float  g_c0[V_*H_];
__device__ __half g_Hm[22080*H_];       // memo: level-0 h by triple index
__device__ float  g_Cm[22080*H_];       // memo: level-0 c
__device__ __half g_HA[B_*1024*H_];     // lvl1,3,5 outputs
__device__ float  g_CA[B_*1024*H_];
__device__ __half g_HB[B_*512*H_];      // lvl2,4 outputs
__device__ float  g_CB[B_*512*H_];
__device__ unsigned g_bar;
__device__ unsigned g_done;

__device__ __forceinline__ float tha(float x){
  float y; asm("tanh.approx.f32 %0, %1;" : "=f"(y) : "f"(x)); return y;
}
__device__ __forceinline__ float sga(float x){ return 0.5f*tha(0.5f*x) + 0.5f; }

__device__ __forceinline__ unsigned saddr(const void* p){
  return (unsigned)__cvta_generic_to_shared(p);
}
__device__ __forceinline__ void ldsm4(unsigned addr, unsigned &r0, unsigned &r1, unsigned &r2, unsigned &r3){
  asm volatile("ldmatrix.sync.aligned.m8n8.x4.shared.b16 {%0,%1,%2,%3}, [%4];"
    : "=r"(r0),"=r"(r1),"=r"(r2),"=r"(r3) : "r"(addr));
}
__device__ __forceinline__ void mma16816(float d[4], const unsigned a[4], unsigned b0, unsigned b1){
  asm volatile("mma.sync.aligned.m16n8k16.row.col.f32.f16.f16.f32 "
    "{%0,%1,%2,%3}, {%4,%5,%6,%7}, {%8,%9}, {%0,%1,%2,%3};"
    : "+f"(d[0]),"+f"(d[1]),"+f"(d[2]),"+f"(d[3])
    : "r"(a[0]),"r"(a[1]),"r"(a[2]),"r"(a[3]), "r"(b0),"r"(b1));
}
__device__ __forceinline__ uint32_t hadd2u(uint32_t a, uint32_t b){
  __half2 r = __hadd2(*reinterpret_cast<__half2*>(&a), *reinterpret_cast<__half2*>(&b));
  return *reinterpret_cast<uint32_t*>(&r);
}
__device__ __forceinline__ uint32_t hsub2u(uint32_t a, uint32_t b){
  __half2 r = __hsub2(*reinterpret_cast<__half2*>(&a), *reinterpret_cast<__half2*>(&b));
  return *reinterpret_cast<uint32_t*>(&r);
}
__device__ __forceinline__ uint4 ldcg4(const uint4* p){
  uint4 v;
  asm volatile("ld.global.cg.v4.u32 {%0,%1,%2,%3}, [%4];"
    : "=r"(v.x),"=r"(v.y),"=r"(v.z),"=r"(v.w) : "l"(p));
  return v;
}
__device__ __forceinline__ float2 ldcg2f(const float2* p){
  float2 v;
  asm volatile("ld.global.cg.v2.f32 {%0,%1}, [%2];" : "=f"(v.x),"=f"(v.y) : "l"(p));
  return v;
}
__device__ __forceinline__ void stcg2f(float2* p, float2 v){
  asm volatile("st.global.cg.v2.f32 [%0], {%1,%2};" :: "l"(p), "f"(v.x), "f"(v.y) : "memory");
}
__device__ __forceinline__ void stcgu(uint32_t* p, uint32_t v){
  asm volatile("st.global.cg.u32 [%0], %1;" :: "l"(p), "r"(v) : "memory");
}

// memo index of leaf-pair node (b, jj) at the 2048-node level
__device__ __forceinline__ int memo_idx(const int* __restrict__ tokens,
                                        const int* __restrict__ symbols, int b, int jj){
  int ta = __ldg(&tokens[b*N_ + 2*jj]);
  int tb = __ldg(&tokens[b*N_ + 2*jj + 1]);
  int sy = __ldg(&symbols[b*(N_-1) + jj]);
  return (ta*V_ + tb)*S_ + sy;
}

// ---------------- shared GEMM tile ----------------
__device__ __forceinline__ void gemm_tile(const __half* sU, const __half* sHT, const __half* sHR,
                                          int lane, int wm, int wn,
                                          float acc1[12][4], float acc2[8][4]){
  #pragma unroll
  for (int i = 0; i < 12; i++){ acc1[i][0]=0.f; acc1[i][1]=0.f; acc1[i][2]=0.f; acc1[i][3]=0.f; }
  #pragma unroll
  for (int i = 0; i < 8; i++){ acc2[i][0]=0.f; acc2[i][1]=0.f; acc2[i][2]=0.f; acc2[i][3]=0.f; }
  #pragma unroll
  for (int k16 = 0; k16 < 8; k16++){
    const int kh = k16*16;
    const int arow = 16*wm + (lane & 15);
    const int acol = kh + (lane >> 4)*8;
    unsigned aT[4], aR[4], aL[4];
    ldsm4(saddr(&sHT[arow*PADH + acol]), aT[0],aT[1],aT[2],aT[3]);
    ldsm4(saddr(&sHR[arow*PADH + acol]), aR[0],aR[1],aR[2],aR[3]);
    #pragma unroll
    for (int i = 0; i < 4; i++) aL[i] = hsub2u(aT[i], aR[i]);   // hl = ht - hr

    const int brow_in = ((lane>>4)&1)*8 + (lane&7);
    const int bcol    = kh + ((lane>>3)&1)*8;
    #pragma unroll
    for (int g = 0; g < 3; g++){
      #pragma unroll
      for (int sp = 0; sp < 2; sp++){
        int R0 = 128*g + 32*wn + 16*sp;
        unsigned r0,r1,r2,r3;
        ldsm4(saddr(&sU[(R0 + brow_in)*PADH + bcol]), r0,r1,r2,r3);
        mma16816(acc1[g*4 + 2*sp + 0], aT, r0, r1);
        mma16816(acc1[g*4 + 2*sp + 1], aT, r2, r3);
      }
    }
    #pragma unroll
    for (int sp = 0; sp < 2; sp++){
      int R0 = 384 + 32*wn + 16*sp;
      unsigned r0,r1,r2,r3;
      ldsm4(saddr(&sU[(R0 + brow_in)*PADH + bcol]), r0,r1,r2,r3);
      mma16816(acc2[2*sp + 0], aL, r0, r1);
      mma16816(acc2[2*sp + 1], aL, r2, r3);
      mma16816(acc2[4 + 2*sp + 0], aR, r0, r1);
      mma16816(acc2[4 + 2*sp + 1], aR, r2, r3);
    }
  }
}

// stage 64-node tile. lvl==0: rows are memo triples from the leaf tables.
// lvl==1: children are memo rows (indices via tokens/symbols). lvl>=2: children 2n,2n+1.
__device__ __forceinline__ void stage_tile(char* bufbase, const __half* Hsrc,
    const int* __restrict__ tokens, const int* __restrict__ symbols,
    int lvl, int node0, int logm, int m, int tid){
  const uint4* H4 = (const uint4*)Hsrc;
  char* sHT = bufbase;
  char* sHR = bufbase + HTILE_BYTES;
  #pragma unroll 2
  for (int idx = tid; idx < 64*16; idx += THREADS){
    int r = idx >> 4, q = idx & 15;
    int n_g = node0 + r;
    int i0 = 0, i1 = 0;
    if (lvl == 0){
      if (n_g < NT0){
        i0 = n_g/(V_*S_);
        int rem = n_g - i0*(V_*S_);
        i1 = rem/S_;
      }
    } else if (lvl == 1){
      int b = n_g >> logm, j = n_g & (m-1);
      i0 = memo_idx(tokens, symbols, b, 2*j);
      i1 = memo_idx(tokens, symbols, b, 2*j + 1);
    } else { i0 = 2*n_g; i1 = 2*n_g + 1; }
    uint4 a  = ldcg4(&H4[i0*16 + q]);
    uint4 b4 = ldcg4(&H4[i1*16 + q]);
    uint4 s;
    s.x = hadd2u(a.x, b4.x); s.y = hadd2u(a.y, b4.y);
    s.z = hadd2u(a.z, b4.z); s.w = hadd2u(a.w, b4.w);
    int boff = r*(PADH*2) + q*16;
    *(uint4*)(sHT + boff) = s;
    *(uint4*)(sHR + boff) = b4;
  }
}

// ---------------- fused persistent kernel ----------------
extern __shared__ char smx[];
__global__ __launch_bounds__(THREADS, 1) void fused_kernel(
  const int* __restrict__ tokens, const int* __restrict__ symbols,
  const float* __restrict__ emb, const float* __restrict__ sym_emb,
  const float* __restrict__ Wp, const float* __restrict__ bp,
  const float* __restrict__ Wi, const float* __restrict__ bi,
  const float* __restrict__ Ui, const float* __restrict__ Wf,
  const float* __restrict__ bf, const float* __restrict__ Uf,
  const float* __restrict__ Wo, const float* __restrict__ bo,
  const float* __restrict__ Uo, const float* __restrict__ Wu,
  const float* __restrict__ bu, const float* __restrict__ Uu,
  const float* __restrict__ Wout, const float* __restrict__ bout,
  float* __restrict__ out)
{
  const int tid = threadIdx.x;
  const int lane = tid & 31, wid = tid >> 5;
  const int wm = wid >> 2, wn = wid & 3;
  __half* sU = (__half*)smx;

  // ---- phase 0: stage fp16 U-concat into smem ----
  for (int idx = tid; idx < 512*32; idx += THREADS){
    int r = idx >> 5, q = idx & 31;
    const float* src = (r < 128) ? Ui + r*H_
                      : (r < 256) ? Uo + (r-128)*H_
                      : (r < 384) ? Uu + (r-256)*H_
                      :             Uf + (r-384)*H_;
    float4 v = __ldg((const float4*)src + q);
    __half2 h0 = __floats2half2_rn(v.x, v.y);
    __half2 h1 = __floats2half2_rn(v.z, v.w);
    uint2 u;
    u.x = *reinterpret_cast<uint32_t*>(&h0);
    u.y = *reinterpret_cast<uint32_t*>(&h1);
    *(uint2*)(smx + (r*PADH + q*4)*2) = u;
  }

  // ---- phase 0b: leaf/symbol tables ----
  if (blockIdx.x < V_ + S_){
    float* se = (float*)(smx + SMU_BYTES);
    float* sx = se + E_;
    const int v_or_s = blockIdx.x;
    const int h = tid;
    if (tid < E_)
      se[tid] = (v_or_s < V_) ? emb[v_or_s*E_ + tid] : sym_emb[(v_or_s - V_)*E_ + tid];
    __syncthreads();
    if (tid < H_){
      float x = bp[h];
      #pragma unroll 8
      for (int e = 0; e < E_; e++) x += se[e]*Wp[h*E_ + e];
      sx[h] = x;
    }
    __syncthreads();
    if (tid < H_){
      if (v_or_s < V_){
        float ai_ = bi[h], ao_ = bo[h], au_ = bu[h];
        #pragma unroll 8
        for (int k = 0; k < H_; k++){
          float xv = sx[k];
          ai_ += xv*Wi[h*H_+k]; ao_ += xv*Wo[h*H_+k]; au_ += xv*Wu[h*H_+k];
        }
        float gi = 1.f/(1.f+expf(-ai_)), go = 1.f/(1.f+expf(-ao_)), gu = tanhf(au_);
        float c = gi*gu;
        g_c0[v_or_s*H_+h] = c;
        g_h016[v_or_s*H_+h] = __float2half(go*tanhf(c));
      } else {
        int s = v_or_s - V_;
        float ai_ = bi[h], ao_ = bo[h], au_ = bu[h], af_ = bf[h];
        #pragma unroll 8
        for (int k = 0; k < H_; k++){
          float xv = sx[k];
          ai_ += xv*Wi[h*H_+k]; ao_ += xv*Wo[h*H_+k];
          au_ += xv*Wu[h*H_+k]; af_ += xv*Wf[h*H_+k];
        }
        g_tai[s*H_+h] = ai_; g_tao[s*H_+h] = ao_;
        g_tau[s*H_+h] = au_; g_taf[s*H_+h] = af_;
      }
    }
  }

  unsigned ep = 0;
  #define GRID_BAR() do { \
    ep++; \
    __syncthreads(); \
    if (tid == 0){ \
      __threadfence(); \
      atomicAdd(&g_bar, 1u); \
      const unsigned tgt = ep*NCTAS; \
      while (*(volatile unsigned*)&g_bar < tgt) __nanosleep(32); \
      __threadfence(); \
    } \
    __syncthreads(); \
  } while(0)

  GRID_BAR();   // tables + U ready

  // =========== level 0: memoized leaf-pair combine over 22050 triples ===========
  {
    const int tiles = T0TILES;
    int t = blockIdx.x;
    int buf = 0;
    if (t < tiles)
      stage_tile(smx + SMU_BYTES + buf*BUF_BYTES, g_h016, tokens, symbols, 0, t << 6, 11, 2048, tid);
    __syncthreads();

    for (; t < tiles; t += NCTAS){
      const int node0 = t << 6;
      char* bb = smx + SMU_BYTES + buf*BUF_BYTES;

      float acc1[12][4], acc2[8][4];
      gemm_tile(sU, (const __half*)bb, (const __half*)(bb + HTILE_BYTES), lane, wm, wn, acc1, acc2);

      {
        int tn = t + NCTAS;
        if (tn < tiles)
          stage_tile(smx + SMU_BYTES + (buf^1)*BUF_BYTES, g_h016, tokens, symbols, 0, tn << 6, 11, 2048, tid);
      }

      // epilogue -> memo tables
      #pragma unroll
      for (int half = 0; half < 2; half++){
        int nl = 16*wm + (lane >> 2) + 8*half;
        int g = node0 + nl;
        bool valid = g < NT0;
        int t0 = 0, t1 = 0, sym = 0;
        if (valid){
          t0 = g/(V_*S_);
          int rem = g - t0*(V_*S_);
          t1 = rem/S_;
          sym = rem - t1*S_;
        }
        const float2* cl2p = (const float2*)(g_c0 + t0*H_);
        const float2* cr2p = (const float2*)(g_c0 + t1*H_);
        const float2* ai2  = (const float2*)(g_tai + sym*H_);
        const float2* ao2  = (const float2*)(g_tao + sym*H_);
        const float2* au2  = (const float2*)(g_tau + sym*H_);
        const float2* af2  = (const float2*)(g_taf + sym*H_);
        float2*  co = (float2*)(g_Cm + (size_t)g*H_);
        uint32_t* ho = (uint32_t*)(g_Hm + (size_t)g*H_);
        const int e = 2*half;
        float2 cl[4], cr[4], tf[4];
        #pragma unroll
        for (int s = 0; s < 4; s++){
          int c2 = 16*wn + 4*s + (lane & 3);
          cl[s] = ldcg2f(cl2p + c2);
          cr[s] = ldcg2f(cr2p + c2);
          tf[s] = __ldg(af2 + c2);
        }
        #pragma unroll
        for (int s = 0; s < 4; s++){
          int c2 = 16*wn + 4*s + (lane & 3);
          float2 ta = __ldg(ai2 + c2), tu = __ldg(au2 + c2), to = __ldg(ao2 + c2);
          float pi0 = acc1[0*4+s][e]   + ta.x, pi1 = acc1[0*4+s][e+1] + ta.y;
          float pu0 = acc1[2*4+s][e]   + tu.x, pu1 = acc1[2*4+s][e+1] + tu.y;
          float fl0 = acc2[s][e]       + tf[s].x, fl1 = acc2[s][e+1]   + tf[s].y;
          float fr0 = acc2[4+s][e]     + tf[s].x, fr1 = acc2[4+s][e+1] + tf[s].y;
          float cn0 = sga(pi0)*tha(pu0) + sga(fl0)*cl[s].x + sga(fr0)*cr[s].x;
          float cn1 = sga(pi1)*tha(pu1) + sga(fl1)*cl[s].y + sga(fr1)*cr[s].y;
          float po0 = acc1[1*4+s][e]   + to.x, po1 = acc1[1*4+s][e+1] + to.y;
          float h0 = sga(po0)*tha(cn0);
          float h1 = sga(po1)*tha(cn1);
          if (valid){
            stcg2f(co + c2, make_float2(cn0, cn1));
            __half2 hh = __floats2half2_rn(h0, h1);
            stcgu(ho + c2, *reinterpret_cast<uint32_t*>(&hh));
          }
        }
      }
      __syncthreads();
      buf ^= 1;
    }
  }
  GRID_BAR();

  // =========== levels 1..5 (m = 1024..64) ===========
  int m = 1024, off = 2048;
  for (int lvl = 1; lvl < 6; lvl++){
    const __half* Hsrc; const float* Csrc;
    __half* Hdst; float* Cdst;
    if (lvl == 1)      { Hsrc = g_Hm; Csrc = g_Cm; }
    else if (lvl & 1)  { Hsrc = g_HB; Csrc = g_CB; }   // lvl3,5 read lvl2,4 output
    else               { Hsrc = g_HA; Csrc = g_CA; }   // lvl2,4 read lvl1,3 output
    if (lvl & 1) { Hdst = g_HA; Cdst = g_CA; } else { Hdst = g_HB; Cdst = g_CB; }

    const int tiles = (B_*m) >> 6;
    const int logm  = 31 - __clz(m);

    int t = blockIdx.x;
    int buf = 0;
    if (t < tiles)
      stage_tile(smx + SMU_BYTES + buf*BUF_BYTES, Hsrc, tokens, symbols, lvl, t << 6, logm, m, tid);
    __syncthreads();

    for (; t < tiles; t += NCTAS){
      const int node0 = t << 6;
      char* bb = smx + SMU_BYTES + buf*BUF_BYTES;

      float acc1[12][4], acc2[8][4];
      gemm_tile(sU, (const __half*)bb, (const __half*)(bb + HTILE_BYTES), lane, wm, wn, acc1, acc2);

      {
        int tn = t + NCTAS;
        if (tn < tiles)
          stage_tile(smx + SMU_BYTES + (buf^1)*BUF_BYTES, Hsrc, tokens, symbols, lvl, tn << 6, logm, m, tid);
      }

      // epilogue
      #pragma unroll
      for (int half = 0; half < 2; half++){
        int nl = 16*wm + (lane >> 2) + 8*half;
        int n_g = node0 + nl;
        int b = n_g >> logm, j = n_g & (m-1);
        int sym = __ldg(&symbols[b*(N_-1) + off + j]);
        int i0, i1;
        if (lvl == 1){
          i0 = memo_idx(tokens, symbols, b, 2*j);
          i1 = memo_idx(tokens, symbols, b, 2*j + 1);
        } else { i0 = 2*n_g; i1 = 2*n_g + 1; }
        const float2* cl2p = (const float2*)(Csrc + (size_t)i0*H_);
        const float2* cr2p = (const float2*)(Csrc + (size_t)i1*H_);
        const float2* ai2  = (const float2*)(g_tai + sym*H_);
        const float2* ao2  = (const float2*)(g_tao + sym*H_);
        const float2* au2  = (const float2*)(g_tau + sym*H_);
        const float2* af2  = (const float2*)(g_taf + sym*H_);
        float2*  co = (float2*)(Cdst + (size_t)n_g*H_);
        uint32_t* ho = (uint32_t*)(Hdst + (size_t)n_g*H_);
        const int e = 2*half;
        float2 cl[4], cr[4], tf[4];
        #pragma unroll
        for (int s = 0; s < 4; s++){
          int c2 = 16*wn + 4*s + (lane & 3);
          cl[s] = ldcg2f(cl2p + c2);
          cr[s] = ldcg2f(cr2p + c2);
          tf[s] = __ldg(af2 + c2);
        }
        #pragma unroll
        for (int s = 0; s < 4; s++){
          int c2 = 16*wn + 4*s + (lane & 3);
          float2 ta = __ldg(ai2 + c2), tu = __ldg(au2 + c2), to = __ldg(ao2 + c2);
          float pi0 = acc1[0*4+s][e]   + ta.x, pi1 = acc1[0*4+s][e+1] + ta.y;
          float pu0 = acc1[2*4+s][e]   + tu.x, pu1 = acc1[2*4+s][e+1] + tu.y;
          float fl0 = acc2[s][e]       + tf[s].x, fl1 = acc2[s][e+1]   + tf[s].y;
          float fr0 = acc2[4+s][e]     + tf[s].x, fr1 = acc2[4+s][e+1] + tf[s].y;
          float cn0 = sga(pi0)*tha(pu0) + sga(fl0)*cl[s].x + sga(fr0)*cr[s].x;
          float cn1 = sga(pi1)*tha(pu1) + sga(fl1)*cl[s].y + sga(fr1)*cr[s].y;
          float po0 = acc1[1*4+s][e]   + to.x, po1 = acc1[1*4+s][e+1] + to.y;
          float h0 = sga(po0)*tha(cn0);
          float h1 = sga(po1)*tha(cn1);
          stcg2f(co + c2, make_float2(cn0, cn1));
          __half2 hh = __floats2half2_rn(h0, h1);
          stcgu(ho + c2, *reinterpret_cast<uint32_t*>(&hh));
        }
      }
      __syncthreads();
      buf ^= 1;
    }

    off += m; m >>= 1;
    if (lvl < 5) GRID_BAR();
    // no barrier after lvl5: CTA b (<64) produced exactly tile b that it consumes next
  }

  // ---- deep phase: per-batch CTA, m = 32..1, all in smem ----
  if (blockIdx.x < B_){
    const int b = blockIdx.x;
    char* dpH = smx + SMU_BYTES + DP_H;
    char* dpC = smx + SMU_BYTES + DP_C;
    char* dpHT = smx + SMU_BYTES + DP_A;
    char* dpHR = dpHT + 8704;
    float* sRoot = (float*)(smx + SMU_BYTES + DP_ROOT);

    // pull this batch's 64 children (lvl5 output in g_HA/g_CA rows b*64..+63)
    {
      const uint4* HS = (const uint4*)g_HA;
      for (int idx = tid; idx < 64*16; idx += THREADS){
        int r = idx >> 4, q = idx & 15;
        *(uint4*)(dpH + r*256 + q*16) = ldcg4(&HS[(b*64 + r)*16 + q]);
      }
      const uint4* CS = (const uint4*)g_CA;
      for (int idx = tid; idx < 64*32; idx += THREADS){
        int r = idx >> 5, q = idx & 31;
        *(uint4*)(dpC + r*512 + q*16) = ldcg4(&CS[(b*64 + r)*32 + q]);
      }
    }
    __syncthreads();

    int offd = 4032;
    for (int dm = 32; dm >= 1; dm >>= 1){
      for (int idx = tid; idx < dm*16; idx += THREADS){
        int r = idx >> 4, q = idx & 15;
        uint4 a  = *(const uint4*)(dpH + (2*r)*256 + q*16);
        uint4 b4 = *(const uint4*)(dpH + (2*r+1)*256 + q*16);
        uint4 s;
        s.x = hadd2u(a.x, b4.x); s.y = hadd2u(a.y, b4.y);
        s.z = hadd2u(a.z, b4.z); s.w = hadd2u(a.w, b4.w);
        int boff = r*(PADH*2) + q*16;
        *(uint4*)(dpHT + boff) = s;
        *(uint4*)(dpHR + boff) = b4;
      }
      __syncthreads();

      const int nrb = (dm + 15) >> 4;
      const bool part = (wm < nrb);
      float acc1[12][4], acc2[8][4];
      if (part)
        gemm_tile(sU, (const __half*)dpHT, (const __half*)dpHR, lane, wm, wn, acc1, acc2);

      float2 cpl[2][4], cpr[2][4];
      if (part){
        #pragma unroll
        for (int half = 0; half < 2; half++){
          int nl = 16*wm + (lane >> 2) + 8*half;
          if (nl < dm){
            #pragma unroll
            for (int s = 0; s < 4; s++){
              int c2 = 16*wn + 4*s + (lane & 3);
              cpl[half][s] = ((const float2*)(dpC + (2*nl)*512))[c2];
              cpr[half][s] = ((const float2*)(dpC + (2*nl+1)*512))[c2];
            }
          }
        }
      }
      __syncthreads();

      if (part){
        #pragma unroll
        for (int half = 0; half < 2; half++){
          int nl = 16*wm + (lane >> 2) + 8*half;
          if (nl >= dm) continue;
          int sym = __ldg(&symbols[b*(N_-1) + offd + nl]);
          const float2* ai2 = (const float2*)(g_tai + sym*H_);
          const float2* ao2 = (const float2*)(g_tao + sym*H_);
          const float2* au2 = (const float2*)(g_tau + sym*H_);
          const float2* af2 = (const float2*)(g_taf + sym*H_);
          float2* co = (float2*)(dpC + nl*512);
          uint32_t* ho = (uint32_t*)(dpH + nl*256);
          const int e = 2*half;
          #pragma unroll
          for (int s = 0; s < 4; s++){
            int c2 = 16*wn + 4*s + (lane & 3);
            float2 ta = __ldg(ai2 + c2), tu = __ldg(au2 + c2);
            float2 tf = __ldg(af2 + c2), to = __ldg(ao2 + c2);
            float pi0 = acc1[0*4+s][e]   + ta.x, pi1 = acc1[0*4+s][e+1] + ta.y;
            float pu0 = acc1[2*4+s][e]   + tu.x, pu1 = acc1[2*4+s][e+1] + tu.y;
            float fl0 = acc2[s][e]       + tf.x, fl1 = acc2[s][e+1]     + tf.y;
            float fr0 = acc2[4+s][e]     + tf.x, fr1 = acc2[4+s][e+1]   + tf.y;
            float cn0 = sga(pi0)*tha(pu0) + sga(fl0)*cpl[half][s].x + sga(fr0)*cpr[half][s].x;
            float cn1 = sga(pi1)*tha(pu1) + sga(fl1)*cpl[half][s].y + sga(fr1)*cpr[half][s].y;
            float po0 = acc1[1*4+s][e]   + to.x, po1 = acc1[1*4+s][e+1] + to.y;
            float h0 = sga(po0)*tha(cn0);
            float h1 = sga(po1)*tha(cn1);
            co[c2] = make_float2(cn0, cn1);
            __half2 hh = __floats2half2_rn(h0, h1);
            ho[c2] = *reinterpret_cast<uint32_t*>(&hh);
            if (dm == 1)
              ((float2*)sRoot)[c2] = make_float2(h0, h1);
          }
        }
      }
      __syncthreads();
      offd += dm;
    }

    // projection for this batch
    if (tid < H_){
      const int o = tid;
      float acc = bout[o];
      const float* w = Wout + o*H_;
      #pragma unroll 8
      for (int k = 0; k < H_; k++) acc += sRoot[k]*w[k];
      out[b*H_ + o] = acc;
    }
  }

  // ---- reset counters for next graph replay ----
  __syncthreads();
  if (tid == 0){
    unsigned d = atomicAdd(&g_done, 1u) + 1u;
    if (d == NCTAS){
      atomicExch(&g_bar, 0u);
      atomicExch(&g_done, 0u);
    }
  }
}

// ---------------- host orchestration ----------------
extern "C" void kernel_launch(void* const* d_in, const int* in_sizes, int n_in,
                              void* d_out, int out_size) {
  const int*   tokens  = (const int*)  d_in[0];
  const int*   symbols = (const int*)  d_in[1];
  const float* emb     = (const float*)d_in[2];
  const float* sym_emb = (const float*)d_in[3];
  const float* Wp   = (const float*)d_in[4];
  const float* bp   = (const float*)d_in[5];
  const float* Wi   = (const float*)d_in[6];
  const float* bi   = (const float*)d_in[7];
  const float* Ui   = (const float*)d_in[8];
  const float* Wf   = (const float*)d_in[9];
  const float* bf   = (const float*)d_in[10];
  const float* Uf   = (const float*)d_in[11];
  const float* Wo   = (const float*)d_in[12];
  const float* bo   = (const float*)d_in[13];
  const float* Uo   = (const float*)d_in[14];
  const float* Wu   = (const float*)d_in[15];
  const float* bu   = (const float*)d_in[16];
  const float* Uu   = (const float*)d_in[17];
  const float* Wout = (const float*)d_in[18];
  const float* bout = (const float*)d_in[19];

  cudaFuncSetAttribute(fused_kernel, cudaFuncAttributeMaxDynamicSharedMemorySize, SM_TOTAL);
  fused_kernel<<<NCTAS, THREADS, SM_TOTAL>>>(
      tokens, symbols, emb, sym_emb, Wp, bp, Wi, bi, Ui, Wf, bf, Uf,
      Wo, bo, Uo, Wu, bu, Uu, Wout, bout, (float*)d_out);
}

// round 9
// speedup vs baseline: 1.5057x; 1.0008x over previous
#include <cuda_runtime.h>
#include <cuda_fp16.h>
#include <stdint.h>
#include <math.h>

#define B_ 64
#define N_ 4096
#define V_ 21
#define S_ 50
#define E_ 64
#define H_ 128
#define THREADS 512
#define NCTAS 148
#define PADH 136      // halves per padded smem row (272B)

#define NT0 22050     // 21*21*50 unique (tokL, tokR, symbol) leaf-pair triples
#define T0TILES 345   // ceil(22050/64)

// smem layout (bytes)
#define SMU_BYTES (512*PADH*2)          // 139264: U-concat
#define HTILE_BYTES (64*PADH*2)         // 17408
#define BUF_BYTES (2*HTILE_BYTES)       // 34816 (HT+HR)
#define SM_TOTAL (SMU_BYTES + 2*BUF_BYTES)   // 208896

// deep-phase layout inside the buffer region (offsets from SMU_BYTES)
#define DP_H    0        // 64 rows x 256B fp16
#define DP_C    16384    // 64 rows x 512B fp32
#define DP_A    49152    // HT 32x272 = 8704, HR 8704
#define DP_ROOT 66560    // 128 floats

// ---------------- static device scratch ----------------
__device__ float  g_tai[S_*H_], g_tao[S_*H_], g_tau[S_*H_], g_taf[S_*H_];
__device__ __half g_h016[V_*H_];
__device__ float  g_c0[V_*H_];
__device__ __half g_Hm[22080*H_];       // memo: level-0 h by triple index
__device__ float  g_Cm[22080*H_];       // memo: level-0 c
__device__ __half g_HA[B_*1024*H_];     // lvl1,3,5 outputs
__device__ float  g_CA[B_*1024*H_];
__device__ __half g_HB[B_*512*H_];      // lvl2,4 outputs
__device__ float  g_CB[B_*512*H_];
__device__ unsigned g_tick[4];          // work-stealing counters lvl0..3
__device__ unsigned g_bar;
__device__ unsigned g_done;

__device__ __forceinline__ float tha(float x){
  float y; asm("tanh.approx.f32 %0, %1;" : "=f"(y) : "f"(x)); return y;
}
__device__ __forceinline__ float sga(float x){ return 0.5f*tha(0.5f*x) + 0.5f; }

__device__ __forceinline__ unsigned saddr(const void* p){
  return (unsigned)__cvta_generic_to_shared(p);
}
__device__ __forceinline__ void ldsm4(unsigned addr, unsigned &r0, unsigned &r1, unsigned &r2, unsigned &r3){
  asm volatile("ldmatrix.sync.aligned.m8n8.x4.shared.b16 {%0,%1,%2,%3}, [%4];"
    : "=r"(r0),"=r"(r1),"=r"(r2),"=r"(r3) : "r"(addr));
}
__device__ __forceinline__ void mma16816(float d[4], const unsigned a[4], unsigned b0, unsigned b1){
  asm volatile("mma.sync.aligned.m16n8k16.row.col.f32.f16.f16.f32 "
    "{%0,%1,%2,%3}, {%4,%5,%6,%7}, {%8,%9}, {%0,%1,%2,%3};"
    : "+f"(d[0]),"+f"(d[1]),"+f"(d[2]),"+f"(d[3])
    : "r"(a[0]),"r"(a[1]),"r"(a[2]),"r"(a[3]), "r"(b0),"r"(b1));
}
__device__ __forceinline__ uint32_t hadd2u(uint32_t a, uint32_t b){
  __half2 r = __hadd2(*reinterpret_cast<__half2*>(&a), *reinterpret_cast<__half2*>(&b));
  return *reinterpret_cast<uint32_t*>(&r);
}
__device__ __forceinline__ uint32_t hsub2u(uint32_t a, uint32_t b){
  __half2 r = __hsub2(*reinterpret_cast<__half2*>(&a), *reinterpret_cast<__half2*>(&b));
  return *reinterpret_cast<uint32_t*>(&r);
}
__device__ __forceinline__ uint4 ldcg4(const uint4* p){
  uint4 v;
  asm volatile("ld.global.cg.v4.u32 {%0,%1,%2,%3}, [%4];"
    : "=r"(v.x),"=r"(v.y),"=r"(v.z),"=r"(v.w) : "l"(p));
  return v;
}
__device__ __forceinline__ float2 ldcg2f(const float2* p){
  float2 v;
  asm volatile("ld.global.cg.v2.f32 {%0,%1}, [%2];" : "=f"(v.x),"=f"(v.y) : "l"(p));
  return v;
}
__device__ __forceinline__ void stcg2f(float2* p, float2 v){
  asm volatile("st.global.cg.v2.f32 [%0], {%1,%2};" :: "l"(p), "f"(v.x), "f"(v.y) : "memory");
}
__device__ __forceinline__ void stcgu(uint32_t* p, uint32_t v){
  asm volatile("st.global.cg.u32 [%0], %1;" :: "l"(p), "r"(v) : "memory");
}

// memo index of leaf-pair node (b, jj) at the 2048-node level
__device__ __forceinline__ int memo_idx(const int* __restrict__ tokens,
                                        const int* __restrict__ symbols, int b, int jj){
  int ta = __ldg(&tokens[b*N_ + 2*jj]);
  int tb = __ldg(&tokens[b*N_ + 2*jj + 1]);
  int sy = __ldg(&symbols[b*(N_-1) + jj]);
  return (ta*V_ + tb)*S_ + sy;
}

// ---------------- shared GEMM tile ----------------
__device__ __forceinline__ void gemm_tile(const __half* sU, const __half* sHT, const __half* sHR,
                                          int lane, int wm, int wn,
                                          float acc1[12][4], float acc2[8][4]){
  #pragma unroll
  for (int i = 0; i < 12; i++){ acc1[i][0]=0.f; acc1[i][1]=0.f; acc1[i][2]=0.f; acc1[i][3]=0.f; }
  #pragma unroll
  for (int i = 0; i < 8; i++){ acc2[i][0]=0.f; acc2[i][1]=0.f; acc2[i][2]=0.f; acc2[i][3]=0.f; }
  #pragma unroll
  for (int k16 = 0; k16 < 8; k16++){
    const int kh = k16*16;
    const int arow = 16*wm + (lane & 15);
    const int acol = kh + (lane >> 4)*8;
    unsigned aT[4], aR[4], aL[4];
    ldsm4(saddr(&sHT[arow*PADH + acol]), aT[0],aT[1],aT[2],aT[3]);
    ldsm4(saddr(&sHR[arow*PADH + acol]), aR[0],aR[1],aR[2],aR[3]);
    #pragma unroll
    for (int i = 0; i < 4; i++) aL[i] = hsub2u(aT[i], aR[i]);   // hl = ht - hr

    const int brow_in = ((lane>>4)&1)*8 + (lane&7);
    const int bcol    = kh + ((lane>>3)&1)*8;
    #pragma unroll
    for (int g = 0; g < 3; g++){
      #pragma unroll
      for (int sp = 0; sp < 2; sp++){
        int R0 = 128*g + 32*wn + 16*sp;
        unsigned r0,r1,r2,r3;
        ldsm4(saddr(&sU[(R0 + brow_in)*PADH + bcol]), r0,r1,r2,r3);
        mma16816(acc1[g*4 + 2*sp + 0], aT, r0, r1);
        mma16816(acc1[g*4 + 2*sp + 1], aT, r2, r3);
      }
    }
    #pragma unroll
    for (int sp = 0; sp < 2; sp++){
      int R0 = 384 + 32*wn + 16*sp;
      unsigned r0,r1,r2,r3;
      ldsm4(saddr(&sU[(R0 + brow_in)*PADH + bcol]), r0,r1,r2,r3);
      mma16816(acc2[2*sp + 0], aL, r0, r1);
      mma16816(acc2[2*sp + 1], aL, r2, r3);
      mma16816(acc2[4 + 2*sp + 0], aR, r0, r1);
      mma16816(acc2[4 + 2*sp + 1], aR, r2, r3);
    }
  }
}

// stage 64-node tile. lvl==0: rows are memo triples from the leaf tables.
// lvl==1: children are memo rows. lvl>=2: children 2n,2n+1.
__device__ __forceinline__ void stage_tile(char* bufbase, const __half* Hsrc,
    const int* __restrict__ tokens, const int* __restrict__ symbols,
    int lvl, int node0, int logm, int m, int tid){
  const uint4* H4 = (const uint4*)Hsrc;
  char* sHT = bufbase;
  char* sHR = bufbase + HTILE_BYTES;
  #pragma unroll 2
  for (int idx = tid; idx < 64*16; idx += THREADS){
    int r = idx >> 4, q = idx & 15;
    int n_g = node0 + r;
    int i0 = 0, i1 = 0;
    if (lvl == 0){
      if (n_g < NT0){
        i0 = n_g/(V_*S_);
        int rem = n_g - i0*(V_*S_);
        i1 = rem/S_;
      }
    } else if (lvl == 1){
      int b = n_g >> logm, j = n_g & (m-1);
      i0 = memo_idx(tokens, symbols, b, 2*j);
      i1 = memo_idx(tokens, symbols, b, 2*j + 1);
    } else { i0 = 2*n_g; i1 = 2*n_g + 1; }
    uint4 a  = ldcg4(&H4[i0*16 + q]);
    uint4 b4 = ldcg4(&H4[i1*16 + q]);
    uint4 s;
    s.x = hadd2u(a.x, b4.x); s.y = hadd2u(a.y, b4.y);
    s.z = hadd2u(a.z, b4.z); s.w = hadd2u(a.w, b4.w);
    int boff = r*(PADH*2) + q*16;
    *(uint4*)(sHT + boff) = s;
    *(uint4*)(sHR + boff) = b4;
  }
}

// epilogue for levels 1..5
__device__ __forceinline__ void epilogue_15(
    const float acc1[12][4], const float acc2[8][4],
    int lvl, int node0, int off, int m, int logm,
    const float* Csrc, __half* Hdst, float* Cdst,
    const int* __restrict__ tokens, const int* __restrict__ symbols,
    int lane, int wm, int wn){
  #pragma unroll
  for (int half = 0; half < 2; half++){
    int nl = 16*wm + (lane >> 2) + 8*half;
    int n_g = node0 + nl;
    int b = n_g >> logm, j = n_g & (m-1);
    int sym = __ldg(&symbols[b*(N_-1) + off + j]);
    int i0, i1;
    if (lvl == 1){
      i0 = memo_idx(tokens, symbols, b, 2*j);
      i1 = memo_idx(tokens, symbols, b, 2*j + 1);
    } else { i0 = 2*n_g; i1 = 2*n_g + 1; }
    const float2* cl2p = (const float2*)(Csrc + (size_t)i0*H_);
    const float2* cr2p = (const float2*)(Csrc + (size_t)i1*H_);
    const float2* ai2  = (const float2*)(g_tai + sym*H_);
    const float2* ao2  = (const float2*)(g_tao + sym*H_);
    const float2* au2  = (const float2*)(g_tau + sym*H_);
    const float2* af2  = (const float2*)(g_taf + sym*H_);
    float2*  co = (float2*)(Cdst + (size_t)n_g*H_);
    uint32_t* ho = (uint32_t*)(Hdst + (size_t)n_g*H_);
    const int e = 2*half;
    float2 cl[4], cr[4], tf[4];
    #pragma unroll
    for (int s = 0; s < 4; s++){
      int c2 = 16*wn + 4*s + (lane & 3);
      cl[s] = ldcg2f(cl2p + c2);
      cr[s] = ldcg2f(cr2p + c2);
      tf[s] = __ldg(af2 + c2);
    }
    #pragma unroll
    for (int s = 0; s < 4; s++){
      int c2 = 16*wn + 4*s + (lane & 3);
      float2 ta = __ldg(ai2 + c2), tu = __ldg(au2 + c2), to = __ldg(ao2 + c2);
      float pi0 = acc1[0*4+s][e]   + ta.x, pi1 = acc1[0*4+s][e+1] + ta.y;
      float pu0 = acc1[2*4+s][e]   + tu.x, pu1 = acc1[2*4+s][e+1] + tu.y;
      float fl0 = acc2[s][e]       + tf[s].x, fl1 = acc2[s][e+1]   + tf[s].y;
      float fr0 = acc2[4+s][e]     + tf[s].x, fr1 = acc2[4+s][e+1] + tf[s].y;
      float cn0 = sga(pi0)*tha(pu0) + sga(fl0)*cl[s].x + sga(fr0)*cr[s].x;
      float cn1 = sga(pi1)*tha(pu1) + sga(fl1)*cl[s].y + sga(fr1)*cr[s].y;
      float po0 = acc1[1*4+s][e]   + to.x, po1 = acc1[1*4+s][e+1] + to.y;
      float h0 = sga(po0)*tha(cn0);
      float h1 = sga(po1)*tha(cn1);
      stcg2f(co + c2, make_float2(cn0, cn1));
      __half2 hh = __floats2half2_rn(h0, h1);
      stcgu(ho + c2, *reinterpret_cast<uint32_t*>(&hh));
    }
  }
}

// ---------------- fused persistent kernel ----------------
extern __shared__ char smx[];
__global__ __launch_bounds__(THREADS, 1) void fused_kernel(
  const int* __restrict__ tokens, const int* __restrict__ symbols,
  const float* __restrict__ emb, const float* __restrict__ sym_emb,
  const float* __restrict__ Wp, const float* __restrict__ bp,
  const float* __restrict__ Wi, const float* __restrict__ bi,
  const float* __restrict__ Ui, const float* __restrict__ Wf,
  const float* __restrict__ bf, const float* __restrict__ Uf,
  const float* __restrict__ Wo, const float* __restrict__ bo,
  const float* __restrict__ Uo, const float* __restrict__ Wu,
  const float* __restrict__ bu, const float* __restrict__ Uu,
  const float* __restrict__ Wout, const float* __restrict__ bout,
  float* __restrict__ out)
{
  const int tid = threadIdx.x;
  const int lane = tid & 31, wid = tid >> 5;
  const int wm = wid >> 2, wn = wid & 3;
  __half* sU = (__half*)smx;
  __shared__ int sTick;

  // ---- phase 0: stage fp16 U-concat into smem ----
  for (int idx = tid; idx < 512*32; idx += THREADS){
    int r = idx >> 5, q = idx & 31;
    const float* src = (r < 128) ? Ui + r*H_
                      : (r < 256) ? Uo + (r-128)*H_
                      : (r < 384) ? Uu + (r-256)*H_
                      :             Uf + (r-384)*H_;
    float4 v = __ldg((const float4*)src + q);
    __half2 h0 = __floats2half2_rn(v.x, v.y);
    __half2 h1 = __floats2half2_rn(v.z, v.w);
    uint2 u;
    u.x = *reinterpret_cast<uint32_t*>(&h0);
    u.y = *reinterpret_cast<uint32_t*>(&h1);
    *(uint2*)(smx + (r*PADH + q*4)*2) = u;
  }

  // ---- phase 0b: leaf/symbol tables ----
  if (blockIdx.x < V_ + S_){
    float* se = (float*)(smx + SMU_BYTES);
    float* sx = se + E_;
    const int v_or_s = blockIdx.x;
    const int h = tid;
    if (tid < E_)
      se[tid] = (v_or_s < V_) ? emb[v_or_s*E_ + tid] : sym_emb[(v_or_s - V_)*E_ + tid];
    __syncthreads();
    if (tid < H_){
      float x = bp[h];
      #pragma unroll 8
      for (int e = 0; e < E_; e++) x += se[e]*Wp[h*E_ + e];
      sx[h] = x;
    }
    __syncthreads();
    if (tid < H_){
      if (v_or_s < V_){
        float ai_ = bi[h], ao_ = bo[h], au_ = bu[h];
        #pragma unroll 8
        for (int k = 0; k < H_; k++){
          float xv = sx[k];
          ai_ += xv*Wi[h*H_+k]; ao_ += xv*Wo[h*H_+k]; au_ += xv*Wu[h*H_+k];
        }
        float gi = 1.f/(1.f+expf(-ai_)), go = 1.f/(1.f+expf(-ao_)), gu = tanhf(au_);
        float c = gi*gu;
        g_c0[v_or_s*H_+h] = c;
        g_h016[v_or_s*H_+h] = __float2half(go*tanhf(c));
      } else {
        int s = v_or_s - V_;
        float ai_ = bi[h], ao_ = bo[h], au_ = bu[h], af_ = bf[h];
        #pragma unroll 8
        for (int k = 0; k < H_; k++){
          float xv = sx[k];
          ai_ += xv*Wi[h*H_+k]; ao_ += xv*Wo[h*H_+k];
          au_ += xv*Wu[h*H_+k]; af_ += xv*Wf[h*H_+k];
        }
        g_tai[s*H_+h] = ai_; g_tao[s*H_+h] = ao_;
        g_tau[s*H_+h] = au_; g_taf[s*H_+h] = af_;
      }
    }
  }

  unsigned ep = 0;
  #define GRID_BAR() do { \
    ep++; \
    __syncthreads(); \
    if (tid == 0){ \
      __threadfence(); \
      atomicAdd(&g_bar, 1u); \
      const unsigned tgt = ep*NCTAS; \
      while (*(volatile unsigned*)&g_bar < tgt) __nanosleep(32); \
      __threadfence(); \
    } \
    __syncthreads(); \
  } while(0)

  GRID_BAR();   // tables + U ready

  // =========== level 0: memoized leaf-pair combine (work stealing) ===========
  {
    const int tiles = T0TILES;
    if (tid == 0) sTick = (int)atomicAdd(&g_tick[0], 1u);
    __syncthreads();
    int t = sTick;
    int buf = 0;
    if (t < tiles)
      stage_tile(smx + SMU_BYTES + buf*BUF_BYTES, g_h016, tokens, symbols, 0, t << 6, 11, 2048, tid);
    if (tid == 0) sTick = (int)atomicAdd(&g_tick[0], 1u);
    __syncthreads();
    int tn = sTick;

    while (t < tiles){
      const int node0 = t << 6;
      char* bb = smx + SMU_BYTES + buf*BUF_BYTES;

      float acc1[12][4], acc2[8][4];
      gemm_tile(sU, (const __half*)bb, (const __half*)(bb + HTILE_BYTES), lane, wm, wn, acc1, acc2);

      if (tn < tiles)
        stage_tile(smx + SMU_BYTES + (buf^1)*BUF_BYTES, g_h016, tokens, symbols, 0, tn << 6, 11, 2048, tid);

      // epilogue -> memo tables
      #pragma unroll
      for (int half = 0; half < 2; half++){
        int nl = 16*wm + (lane >> 2) + 8*half;
        int g = node0 + nl;
        bool valid = g < NT0;
        int t0 = 0, t1 = 0, sym = 0;
        if (valid){
          t0 = g/(V_*S_);
          int rem = g - t0*(V_*S_);
          t1 = rem/S_;
          sym = rem - t1*S_;
        }
        const float2* cl2p = (const float2*)(g_c0 + t0*H_);
        const float2* cr2p = (const float2*)(g_c0 + t1*H_);
        const float2* ai2  = (const float2*)(g_tai + sym*H_);
        const float2* ao2  = (const float2*)(g_tao + sym*H_);
        const float2* au2  = (const float2*)(g_tau + sym*H_);
        const float2* af2  = (const float2*)(g_taf + sym*H_);
        float2*  co = (float2*)(g_Cm + (size_t)g*H_);
        uint32_t* ho = (uint32_t*)(g_Hm + (size_t)g*H_);
        const int e = 2*half;
        float2 cl[4], cr[4], tf[4];
        #pragma unroll
        for (int s = 0; s < 4; s++){
          int c2 = 16*wn + 4*s + (lane & 3);
          cl[s] = ldcg2f(cl2p + c2);
          cr[s] = ldcg2f(cr2p + c2);
          tf[s] = __ldg(af2 + c2);
        }
        #pragma unroll
        for (int s = 0; s < 4; s++){
          int c2 = 16*wn + 4*s + (lane & 3);
          float2 ta = __ldg(ai2 + c2), tu = __ldg(au2 + c2), to = __ldg(ao2 + c2);
          float pi0 = acc1[0*4+s][e]   + ta.x, pi1 = acc1[0*4+s][e+1] + ta.y;
          float pu0 = acc1[2*4+s][e]   + tu.x, pu1 = acc1[2*4+s][e+1] + tu.y;
          float fl0 = acc2[s][e]       + tf[s].x, fl1 = acc2[s][e+1]   + tf[s].y;
          float fr0 = acc2[4+s][e]     + tf[s].x, fr1 = acc2[4+s][e+1] + tf[s].y;
          float cn0 = sga(pi0)*tha(pu0) + sga(fl0)*cl[s].x + sga(fr0)*cr[s].x;
          float cn1 = sga(pi1)*tha(pu1) + sga(fl1)*cl[s].y + sga(fr1)*cr[s].y;
          float po0 = acc1[1*4+s][e]   + to.x, po1 = acc1[1*4+s][e+1] + to.y;
          float h0 = sga(po0)*tha(cn0);
          float h1 = sga(po1)*tha(cn1);
          if (valid){
            stcg2f(co + c2, make_float2(cn0, cn1));
            __half2 hh = __floats2half2_rn(h0, h1);
            stcgu(ho + c2, *reinterpret_cast<uint32_t*>(&hh));
          }
        }
      }
      if (tid == 0 && tn < tiles) sTick = (int)atomicAdd(&g_tick[0], 1u);
      __syncthreads();
      t = tn; tn = sTick; buf ^= 1;
    }
  }
  GRID_BAR();

  // =========== levels 1..5 (m = 1024..64) ===========
  int m = 1024, off = 2048;
  for (int lvl = 1; lvl < 6; lvl++){
    const __half* Hsrc; const float* Csrc;
    __half* Hdst; float* Cdst;
    if (lvl == 1)      { Hsrc = g_Hm; Csrc = g_Cm; }
    else if (lvl & 1)  { Hsrc = g_HB; Csrc = g_CB; }
    else               { Hsrc = g_HA; Csrc = g_CA; }
    if (lvl & 1) { Hdst = g_HA; Cdst = g_CA; } else { Hdst = g_HB; Cdst = g_CB; }

    const int tiles = (B_*m) >> 6;
    const int logm  = 31 - __clz(m);

    if (lvl <= 3){
      // ---- work stealing ----
      if (tid == 0) sTick = (int)atomicAdd(&g_tick[lvl], 1u);
      __syncthreads();
      int t = sTick;
      int buf = 0;
      if (t < tiles)
        stage_tile(smx + SMU_BYTES + buf*BUF_BYTES, Hsrc, tokens, symbols, lvl, t << 6, logm, m, tid);
      if (tid == 0) sTick = (int)atomicAdd(&g_tick[lvl], 1u);
      __syncthreads();
      int tn = sTick;

      while (t < tiles){
        char* bb = smx + SMU_BYTES + buf*BUF_BYTES;
        float acc1[12][4], acc2[8][4];
        gemm_tile(sU, (const __half*)bb, (const __half*)(bb + HTILE_BYTES), lane, wm, wn, acc1, acc2);

        if (tn < tiles)
          stage_tile(smx + SMU_BYTES + (buf^1)*BUF_BYTES, Hsrc, tokens, symbols, lvl, tn << 6, logm, m, tid);

        epilogue_15(acc1, acc2, lvl, t << 6, off, m, logm, Csrc, Hdst, Cdst,
                    tokens, symbols, lane, wm, wn);

        if (tid == 0 && tn < tiles) sTick = (int)atomicAdd(&g_tick[lvl], 1u);
        __syncthreads();
        t = tn; tn = sTick; buf ^= 1;
      }
    } else {
      // ---- static single wave (tiles <= NCTAS); lvl5 mapping feeds deep phase ----
      int t = blockIdx.x;
      if (t < tiles){
        stage_tile(smx + SMU_BYTES, Hsrc, tokens, symbols, lvl, t << 6, logm, m, tid);
        __syncthreads();
        char* bb = smx + SMU_BYTES;
        float acc1[12][4], acc2[8][4];
        gemm_tile(sU, (const __half*)bb, (const __half*)(bb + HTILE_BYTES), lane, wm, wn, acc1, acc2);
        epilogue_15(acc1, acc2, lvl, t << 6, off, m, logm, Csrc, Hdst, Cdst,
                    tokens, symbols, lane, wm, wn);
        __syncthreads();
      }
    }

    off += m; m >>= 1;
    if (lvl < 5) GRID_BAR();
    // no barrier after lvl5: CTA b (<64) produced exactly tile b that it consumes next
  }

  // ---- deep phase: per-batch CTA, m = 32..1, all in smem ----
  if (blockIdx.x < B_){
    const int b = blockIdx.x;
    char* dpH = smx + SMU_BYTES + DP_H;
    char* dpC = smx + SMU_BYTES + DP_C;
    char* dpHT = smx + SMU_BYTES + DP_A;
    char* dpHR = dpHT + 8704;
    float* sRoot = (float*)(smx + SMU_BYTES + DP_ROOT);

    // pull this batch's 64 children (lvl5 output in g_HA/g_CA rows b*64..+63)
    {
      const uint4* HS = (const uint4*)g_HA;
      for (int idx = tid; idx < 64*16; idx += THREADS){
        int r = idx >> 4, q = idx & 15;
        *(uint4*)(dpH + r*256 + q*16) = ldcg4(&HS[(b*64 + r)*16 + q]);
      }
      const uint4* CS = (const uint4*)g_CA;
      for (int idx = tid; idx < 64*32; idx += THREADS){
        int r = idx >> 5, q = idx & 31;
        *(uint4*)(dpC + r*512 + q*16) = ldcg4(&CS[(b*64 + r)*32 + q]);
      }
    }
    __syncthreads();

    int offd = 4032;
    for (int dm = 32; dm >= 1; dm >>= 1){
      for (int idx = tid; idx < dm*16; idx += THREADS){
        int r = idx >> 4, q = idx & 15;
        uint4 a  = *(const uint4*)(dpH + (2*r)*256 + q*16);
        uint4 b4 = *(const uint4*)(dpH + (2*r+1)*256 + q*16);
        uint4 s;
        s.x = hadd2u(a.x, b4.x); s.y = hadd2u(a.y, b4.y);
        s.z = hadd2u(a.z, b4.z); s.w = hadd2u(a.w, b4.w);
        int boff = r*(PADH*2) + q*16;
        *(uint4*)(dpHT + boff) = s;
        *(uint4*)(dpHR + boff) = b4;
      }
      __syncthreads();

      const int nrb = (dm + 15) >> 4;
      const bool part = (wm < nrb);
      float acc1[12][4], acc2[8][4];
      if (part)
        gemm_tile(sU, (const __half*)dpHT, (const __half*)dpHR, lane, wm, wn, acc1, acc2);

      float2 cpl[2][4], cpr[2][4];
      if (part){
        #pragma unroll
        for (int half = 0; half < 2; half++){
          int nl = 16*wm + (lane >> 2) + 8*half;
          if (nl < dm){
            #pragma unroll
            for (int s = 0; s < 4; s++){
              int c2 = 16*wn + 4*s + (lane & 3);
              cpl[half][s] = ((const float2*)(dpC + (2*nl)*512))[c2];
              cpr[half][s] = ((const float2*)(dpC + (2*nl+1)*512))[c2];
            }
          }
        }
      }
      __syncthreads();

      if (part){
        #pragma unroll
        for (int half = 0; half < 2; half++){
          int nl = 16*wm + (lane >> 2) + 8*half;
          if (nl >= dm) continue;
          int sym = __ldg(&symbols[b*(N_-1) + offd + nl]);
          const float2* ai2 = (const float2*)(g_tai + sym*H_);
          const float2* ao2 = (const float2*)(g_tao + sym*H_);
          const float2* au2 = (const float2*)(g_tau + sym*H_);
          const float2* af2 = (const float2*)(g_taf + sym*H_);
          float2* co = (float2*)(dpC + nl*512);
          uint32_t* ho = (uint32_t*)(dpH + nl*256);
          const int e = 2*half;
          #pragma unroll
          for (int s = 0; s < 4; s++){
            int c2 = 16*wn + 4*s + (lane & 3);
            float2 ta = __ldg(ai2 + c2), tu = __ldg(au2 + c2);
            float2 tf = __ldg(af2 + c2), to = __ldg(ao2 + c2);
            float pi0 = acc1[0*4+s][e]   + ta.x, pi1 = acc1[0*4+s][e+1] + ta.y;
            float pu0 = acc1[2*4+s][e]   + tu.x, pu1 = acc1[2*4+s][e+1] + tu.y;
            float fl0 = acc2[s][e]       + tf.x, fl1 = acc2[s][e+1]     + tf.y;
            float fr0 = acc2[4+s][e]     + tf.x, fr1 = acc2[4+s][e+1]   + tf.y;
            float cn0 = sga(pi0)*tha(pu0) + sga(fl0)*cpl[half][s].x + sga(fr0)*cpr[half][s].x;
            float cn1 = sga(pi1)*tha(pu1) + sga(fl1)*cpl[half][s].y + sga(fr1)*cpr[half][s].y;
            float po0 = acc1[1*4+s][e]   + to.x, po1 = acc1[1*4+s][e+1] + to.y;
            float h0 = sga(po0)*tha(cn0);
            float h1 = sga(po1)*tha(cn1);
            co[c2] = make_float2(cn0, cn1);
            __half2 hh = __floats2half2_rn(h0, h1);
            ho[c2] = *reinterpret_cast<uint32_t*>(&hh);
            if (dm == 1)
              ((float2*)sRoot)[c2] = make_float2(h0, h1);
          }
        }
      }
      __syncthreads();
      offd += dm;
    }

    // projection for this batch
    if (tid < H_){
      const int o = tid;
      float acc = bout[o];
      const float* w = Wout + o*H_;
      #pragma unroll 8
      for (int k = 0; k < H_; k++) acc += sRoot[k]*w[k];
      out[b*H_ + o] = acc;
    }
  }

  // ---- reset counters for next graph replay ----
  __syncthreads();
  if (tid == 0){
    unsigned d = atomicAdd(&g_done, 1u) + 1u;
    if (d == NCTAS){
      atomicExch(&g_bar, 0u);
      atomicExch(&g_done, 0u);
      atomicExch(&g_tick[0], 0u);
      atomicExch(&g_tick[1], 0u);
      atomicExch(&g_tick[2], 0u);
      atomicExch(&g_tick[3], 0u);
    }
  }
}

// ---------------- host orchestration ----------------
extern "C" void kernel_launch(void* const* d_in, const int* in_sizes, int n_in,
                              void* d_out, int out_size) {
  const int*   tokens  = (const int*)  d_in[0];
  const int*   symbols = (const int*)  d_in[1];
  const float* emb     = (const float*)d_in[2];
  const float* sym_emb = (const float*)d_in[3];
  const float* Wp   = (const float*)d_in[4];
  const float* bp   = (const float*)d_in[5];
  const float* Wi   = (const float*)d_in[6];
  const float* bi   = (const float*)d_in[7];
  const float* Ui   = (const float*)d_in[8];
  const float* Wf   = (const float*)d_in[9];
  const float* bf   = (const float*)d_in[10];
  const float* Uf   = (const float*)d_in[11];
  const float* Wo   = (const float*)d_in[12];
  const float* bo   = (const float*)d_in[13];
  const float* Uo   = (const float*)d_in[14];
  const float* Wu   = (const float*)d_in[15];
  const float* bu   = (const float*)d_in[16];
  const float* Uu   = (const float*)d_in[17];
  const float* Wout = (const float*)d_in[18];
  const float* bout = (const float*)d_in[19];

  cudaFuncSetAttribute(fused_kernel, cudaFuncAttributeMaxDynamicSharedMemorySize, SM_TOTAL);
  fused_kernel<<<NCTAS, THREADS, SM_TOTAL>>>(
      tokens, symbols, emb, sym_emb, Wp, bp, Wi, bi, Ui, Wf, bf, Uf,
      Wo, bo, Uo, Wu, bu, Uu, Wout, bout, (float*)d_out);
}